// round 14
// baseline (speedup 1.0000x reference)
#include <cuda_runtime.h>
#include <math.h>

#define Hdim   1024
#define H2     512
#define Cdim   256
#define Msize  100000
#define Nsamp  1024
#define Tlen   1024
#define G3     3072
#define RCTAS  64           // CTAs per layer (total grid = 128)
#define RUPC   16           // hidden units per CTA (one per warp, 512 threads)

// ---------------- scratch (static __device__, no allocs) ----------------
__device__ __align__(16) float d_samples[Nsamp * Hdim];
__device__ __align__(16) float d_e1[Nsamp * H2];
__device__ __align__(16) float d_encoded[Nsamp * H2];
__device__ __align__(16) float d_zbuf[Nsamp * Cdim];
__device__ __align__(16) float d_d1[Nsamp * H2];
__device__ __align__(16) float d_recon[Nsamp * Hdim];
__device__ __align__(16) float d_gx[Tlen * G3];        // layer-0 input gates (GEMM)
__device__ __align__(16) float d_gx1[Tlen * G3];       // layer-1 r,z input gates (fused)
__device__ __align__(16) float d_y1[Tlen * Hdim];      // layer-0 outputs (for n-gate)
__device__ __align__(16) float d_wout[Tlen * Hdim];
__device__ float d_toterr[Nsamp];
__device__ __align__(16) float g_h0[2][Hdim];
__device__ __align__(16) float g_h1[2][Hdim];
__device__ unsigned cnt0[Tlen + 1];
__device__ unsigned cnt1[Tlen];

__device__ __forceinline__ float gelu_exact(float x) {
    return 0.5f * x * (1.0f + erff(x * 0.7071067811865476f));
}
__device__ __forceinline__ float sigmoidf_(float x) {
    return 1.0f / (1.0f + expf(-x));
}
__device__ __forceinline__ void red_add_release(unsigned* p, unsigned v) {
    asm volatile("red.add.release.gpu.global.u32 [%0], %1;" :: "l"(p), "r"(v) : "memory");
}
__device__ __forceinline__ unsigned ld_acquire(const unsigned* p) {
    unsigned v;
    asm volatile("ld.acquire.gpu.global.u32 %0, [%1];" : "=r"(v) : "l"(p) : "memory");
    return v;
}

// ---------------- init / small utility kernels ----------------
__global__ void init_kernel() {
    int i = blockIdx.x * blockDim.x + threadIdx.x;    // 8 x 256 = 2048
    if (i < 2 * Hdim) {
        ((float*)g_h0)[i] = 0.0f;
        ((float*)g_h1)[i] = 0.0f;
    }
    if (i < Tlen + 1) cnt0[i] = 0u;
    if (i < Tlen) cnt1[i] = 0u;
}

__global__ void gather_kernel(const float* __restrict__ mem, const int* __restrict__ idx) {
    int n = blockIdx.x;                               // 1024 blocks, 256 threads
    const float4* src = (const float4*)(mem + (size_t)idx[n] * Hdim);
    float4* dst = (float4*)(d_samples + (size_t)n * Hdim);
    dst[threadIdx.x] = src[threadIdx.x];
}

// ---------------- SGEMM 128x128x8, double-buffered: C = A@W^T + bias -------
#define TBM 128
#define TBN 128
#define TBK 8
__global__ void __launch_bounds__(256)
sgemm_bias_kernel(const float* __restrict__ A, const float* __restrict__ W,
                  const float* __restrict__ bias, float* __restrict__ C,
                  int M, int N, int K) {
    __shared__ float As[2][TBK][TBM];
    __shared__ float Bs[2][TBK][TBN];
    const int tid = threadIdx.x;                      // 256
    const int tx = tid & 15, ty = tid >> 4;
    const int row0 = blockIdx.y * TBM, col0 = blockIdx.x * TBN;
    const int lr = tid >> 1;                          // 0..127
    const int lk = (tid & 1) * 4;                     // 0 or 4
    const float* Ap = A + (size_t)(row0 + lr) * K + lk;
    const float* Wp = W + (size_t)(col0 + lr) * K + lk;

    {
        float4 a = *(const float4*)Ap;
        float4 b = *(const float4*)Wp;
        As[0][lk + 0][lr] = a.x; As[0][lk + 1][lr] = a.y;
        As[0][lk + 2][lr] = a.z; As[0][lk + 3][lr] = a.w;
        Bs[0][lk + 0][lr] = b.x; Bs[0][lk + 1][lr] = b.y;
        Bs[0][lk + 2][lr] = b.z; Bs[0][lk + 3][lr] = b.w;
    }
    __syncthreads();

    float acc[8][8];
#pragma unroll
    for (int i = 0; i < 8; i++)
#pragma unroll
        for (int j = 0; j < 8; j++) acc[i][j] = 0.0f;

    const int nIter = K / TBK;
    int cur = 0;
    for (int it = 0; it < nIter; ++it) {
        float4 an, bn;
        const bool more = (it + 1 < nIter);
        if (more) {
            an = *(const float4*)(Ap + (it + 1) * TBK);
            bn = *(const float4*)(Wp + (it + 1) * TBK);
        }
#pragma unroll
        for (int k = 0; k < TBK; k++) {
            float af[8], bf[8];
            *(float4*)&af[0] = *(const float4*)&As[cur][k][ty * 8];
            *(float4*)&af[4] = *(const float4*)&As[cur][k][ty * 8 + 4];
            *(float4*)&bf[0] = *(const float4*)&Bs[cur][k][tx * 8];
            *(float4*)&bf[4] = *(const float4*)&Bs[cur][k][tx * 8 + 4];
#pragma unroll
            for (int i = 0; i < 8; i++)
#pragma unroll
                for (int j = 0; j < 8; j++) acc[i][j] += af[i] * bf[j];
        }
        if (more) {
            int nxt = cur ^ 1;
            As[nxt][lk + 0][lr] = an.x; As[nxt][lk + 1][lr] = an.y;
            As[nxt][lk + 2][lr] = an.z; As[nxt][lk + 3][lr] = an.w;
            Bs[nxt][lk + 0][lr] = bn.x; Bs[nxt][lk + 1][lr] = bn.y;
            Bs[nxt][lk + 2][lr] = bn.z; Bs[nxt][lk + 3][lr] = bn.w;
            __syncthreads();
            cur = nxt;
        }
    }

    float bc[8];
#pragma unroll
    for (int j = 0; j < 8; j++) bc[j] = bias[col0 + tx * 8 + j];
#pragma unroll
    for (int i = 0; i < 8; i++) {
        float* Cr = C + (size_t)(row0 + ty * 8 + i) * N + col0 + tx * 8;
        float4 v0 = make_float4(acc[i][0] + bc[0], acc[i][1] + bc[1],
                                acc[i][2] + bc[2], acc[i][3] + bc[3]);
        float4 v1 = make_float4(acc[i][4] + bc[4], acc[i][5] + bc[5],
                                acc[i][6] + bc[6], acc[i][7] + bc[7]);
        *(float4*)Cr = v0;
        *(float4*)(Cr + 4) = v1;
    }
}

// ---------------- LayerNorm(512) + exact GELU, in place ----------------
__global__ void ln_gelu_kernel(float* __restrict__ x, const float* __restrict__ g,
                               const float* __restrict__ b) {
    int row = blockIdx.x, tid = threadIdx.x;          // 128 threads, 4 elems each
    float4* xr = (float4*)(x + (size_t)row * H2);
    float4 v = xr[tid];
    float s = v.x + v.y + v.z + v.w;
    __shared__ float red[8];
#pragma unroll
    for (int o = 16; o > 0; o >>= 1) s += __shfl_xor_sync(0xffffffffu, s, o);
    if ((tid & 31) == 0) red[tid >> 5] = s;
    __syncthreads();
    float mean = (red[0] + red[1] + red[2] + red[3]) * (1.0f / 512.0f);
    float dx = v.x - mean, dy = v.y - mean, dz = v.z - mean, dw = v.w - mean;
    float q = dx * dx + dy * dy + dz * dz + dw * dw;
#pragma unroll
    for (int o = 16; o > 0; o >>= 1) q += __shfl_xor_sync(0xffffffffu, q, o);
    if ((tid & 31) == 0) red[4 + (tid >> 5)] = q;
    __syncthreads();
    float var = (red[4] + red[5] + red[6] + red[7]) * (1.0f / 512.0f);
    float rstd = rsqrtf(var + 1e-5f);
    float4 gg = ((const float4*)g)[tid];
    float4 bb = ((const float4*)b)[tid];
    v.x = gelu_exact(dx * rstd * gg.x + bb.x);
    v.y = gelu_exact(dy * rstd * gg.y + bb.y);
    v.z = gelu_exact(dz * rstd * gg.z + bb.z);
    v.w = gelu_exact(dw * rstd * gg.w + bb.w);
    xr[tid] = v;
}

// ---------------- reparameterize ----------------
__global__ void reparam_kernel(const float* __restrict__ eps) {
    int i = blockIdx.x * blockDim.x + threadIdx.x;    // N*C = 262144
    if (i < Nsamp * Cdim) {
        int n = i >> 8, c = i & 255;
        float mu = d_encoded[(size_t)n * H2 + c];
        float lv = d_encoded[(size_t)n * H2 + 256 + c];
        d_zbuf[i] = mu + expf(0.5f * lv) * eps[i];
    }
}

// ---------------- pipelined 2-layer GRU recurrence ----------------
// Grid = 128 CTAs x 512 threads, all co-resident.
// CTAs 0..63   (role 0): layer-0 recurrence; gx1 r,z rows (32/CTA) in the spin
//   window (warps 1..15 only — warp 0 arrives at the barrier immediately).
// CTAs 64..127 (role 1): layer-1 recurrence; n-gate inputs computed in ITS spin
//   window by warps 1..15 only (warp 1 also covers unit 0, handed to warp 0
//   through a 1-float smem slot). Thread0's arrival is never delayed.
__global__ void __launch_bounds__(512, 1)
gru_pipe_kernel(const float* __restrict__ whh0, const float* __restrict__ bhh0,
                const float* __restrict__ whh1, const float* __restrict__ bhh1,
                const float* __restrict__ wih1, const float* __restrict__ bih1) {
    extern __shared__ float smem_dyn[];
    const int tid = threadIdx.x;
    const int warp = tid >> 5, lane = tid & 31;
    const bool role1 = (blockIdx.x >= RCTAS);
    const int cid = role1 ? (blockIdx.x - RCTAS) : blockIdx.x;
    const int u = cid * RUPC + warp;
    const float* whh = role1 ? whh1 : whh0;
    const float* bhh = role1 ? bhh1 : bhh0;

    // whh rows (r,z,n) for unit u -> registers. lane l owns cols k = 4l + 128j.
    float4 wr[8], wz[8], wn[8];
#pragma unroll
    for (int j = 0; j < 8; j++) {
        int k = 4 * lane + 128 * j;
        wr[j] = __ldg((const float4*)(whh + (size_t)(0 * Hdim + u) * Hdim + k));
        wz[j] = __ldg((const float4*)(whh + (size_t)(1 * Hdim + u) * Hdim + k));
        wn[j] = __ldg((const float4*)(whh + (size_t)(2 * Hdim + u) * Hdim + k));
    }
    const float br = bhh[u], bz = bhh[Hdim + u], bn = bhh[2 * Hdim + u];

    if (!role1) {
        // ---- layer 0 ----
        float* h_s = smem_dyn;                    // Hdim
        float* w1s = smem_dyn + Hdim;             // 32*Hdim (r,z rows)
        // wih1 r,z rows for units 16*cid..16*cid+15 (32 rows) -> smem
        for (int i = tid; i < 32 * 256; i += 512) {
            int lr = i >> 8, pos = (i & 255) << 2;
            int grow = (lr >> 4) * Hdim + RUPC * cid + (lr & 15);   // gate 0/1
            *(float4*)(w1s + lr * Hdim + pos) =
                __ldg((const float4*)(wih1 + (size_t)grow * Hdim + pos));
        }
        // warps 1..15 handle rows base, base+15, base+30(if<32); base = warp-1
        const int base = warp - 1;
        float b1a = 0.f, b1b = 0.f, b1c = 0.f;
        if (warp >= 1) {
            b1a = bih1[(base >> 4) * Hdim + RUPC * cid + (base & 15)];
            b1b = bih1[((base + 15) >> 4) * Hdim + RUPC * cid + ((base + 15) & 15)];
            if (base + 30 < 32)
                b1c = bih1[((base + 30) >> 4) * Hdim + RUPC * cid + ((base + 30) & 15)];
        }
        __syncthreads();

        auto gx1_rows = [&](int tout) {
            const float* r0 = w1s + base * Hdim;
            const float* r1 = w1s + (base + 15) * Hdim;
            const float* r2 = (base + 30 < 32) ? (w1s + (base + 30) * Hdim) : r0;
            float p0 = 0.f, p1 = 0.f, p2 = 0.f;
#pragma unroll
            for (int j = 0; j < 8; ++j) {
                int p = lane + 32 * j;
                float4 h4 = ((const float4*)h_s)[p];
                float4 a = ((const float4*)r0)[p];
                float4 b = ((const float4*)r1)[p];
                float4 c = ((const float4*)r2)[p];
                p0 += a.x * h4.x + a.y * h4.y + a.z * h4.z + a.w * h4.w;
                p1 += b.x * h4.x + b.y * h4.y + b.z * h4.z + b.w * h4.w;
                p2 += c.x * h4.x + c.y * h4.y + c.z * h4.z + c.w * h4.w;
            }
#pragma unroll
            for (int o = 16; o > 0; o >>= 1) {
                p0 += __shfl_xor_sync(0xffffffffu, p0, o);
                p1 += __shfl_xor_sync(0xffffffffu, p1, o);
                p2 += __shfl_xor_sync(0xffffffffu, p2, o);
            }
            if (lane == 0) {
                size_t ob = (size_t)tout * G3;
                d_gx1[ob + (base >> 4) * Hdim + RUPC * cid + (base & 15)] = p0 + b1a;
                d_gx1[ob + ((base + 15) >> 4) * Hdim + RUPC * cid + ((base + 15) & 15)] = p1 + b1b;
                if (base + 30 < 32)
                    d_gx1[ob + ((base + 30) >> 4) * Hdim + RUPC * cid + ((base + 30) & 15)] = p2 + b1c;
            }
        };

        float gxr = __ldg(d_gx + u), gxz = __ldg(d_gx + Hdim + u),
              gxn = __ldg(d_gx + 2 * Hdim + u);

        for (int t = 0; t < Tlen; ++t) {
            if (tid < 256) {
                float4 v = __ldcg(((const float4*)g_h0[t & 1]) + tid);
                *(float4*)(h_s + tid * 4) = v;
            }
            __syncthreads();
            float sr = 0.f, sz = 0.f, sn = 0.f;
#pragma unroll
            for (int j = 0; j < 8; ++j) {
                float4 h4 = ((const float4*)h_s)[lane + 32 * j];
                sr += wr[j].x * h4.x + wr[j].y * h4.y + wr[j].z * h4.z + wr[j].w * h4.w;
                sz += wz[j].x * h4.x + wz[j].y * h4.y + wz[j].z * h4.z + wz[j].w * h4.w;
                sn += wn[j].x * h4.x + wn[j].y * h4.y + wn[j].z * h4.z + wn[j].w * h4.w;
            }
#pragma unroll
            for (int o = 16; o > 0; o >>= 1) {
                sr += __shfl_xor_sync(0xffffffffu, sr, o);
                sz += __shfl_xor_sync(0xffffffffu, sz, o);
                sn += __shfl_xor_sync(0xffffffffu, sn, o);
            }
            if (lane == 0) {
                float r = sigmoidf_(gxr + sr + br);
                float z = sigmoidf_(gxz + sz + bz);
                float nn = tanhf(gxn + r * (sn + bn));
                float hp = h_s[u];
                float hnew = (1.0f - z) * nn + z * hp;
                g_h0[(t + 1) & 1][u] = hnew;
                d_y1[(size_t)t * Hdim + u] = hnew;    // publish y1[t] for layer-1
            }
            if (t + 1 < Tlen) {
                const float* gp = d_gx + (size_t)(t + 1) * G3;
                gxr = __ldg(gp + u); gxz = __ldg(gp + Hdim + u); gxn = __ldg(gp + 2 * Hdim + u);
            }
            __syncthreads();
            if (t > 0 && warp != 0) gx1_rows(t - 1);   // slack work (h_s = y1[t-1])
            if (tid == 0) {
                red_add_release(&cnt0[t], 1u);
                while (ld_acquire(&cnt0[t]) < (unsigned)RCTAS) { }
            }
            __syncthreads();
        }
        // epilogue: gx1 r,z for [Tlen-1] from h_Tlen
        if (tid < 256) {
            float4 v = __ldcg(((const float4*)g_h0[Tlen & 1]) + tid);
            *(float4*)(h_s + tid * 4) = v;
        }
        __syncthreads();
        if (warp != 0) gx1_rows(Tlen - 1);
        __syncthreads();
        if (tid == 0) red_add_release(&cnt0[Tlen], 1u);
    } else {
        // ---- layer 1 ----
        float* h_s = smem_dyn;                    // Hdim
        float* y_s = smem_dyn + Hdim;             // Hdim (y1[s+1])
        float* w1n = smem_dyn + 2 * Hdim;         // 16*Hdim (own n-gate rows)
        float* gxn0_p = smem_dyn + 18 * Hdim;     // 1 float: unit-0 n-gate handoff
        // own n-gate wih1 rows -> smem; bias -> register
        for (int i = tid; i < 16 * 256; i += 512) {
            int lr = i >> 8, pos = (i & 255) << 2;
            *(float4*)(w1n + lr * Hdim + pos) =
                __ldg((const float4*)(wih1 + (size_t)(2 * Hdim + RUPC * cid + lr) * Hdim + pos));
        }
        const float b1n = bih1[2 * Hdim + u];
        const float b1n0 = (warp == 1) ? bih1[2 * Hdim + RUPC * cid] : 0.0f;
        const float* w1n_row = w1n + warp * Hdim;

        // wait for gx1 r,z [0] (cnt0[2]) which also orders y1[0] (cnt0[1])
        if (tid == 0) {
            while (ld_acquire(&cnt0[2]) < (unsigned)RCTAS) { }
        }
        __syncthreads();
        // pre-loop: gxn[0] for every warp (incl. warp 0 once; off steady path)
        if (tid < 256) {
            float4 v = __ldcg(((const float4*)d_y1) + tid);
            *(float4*)(y_s + tid * 4) = v;
        }
        __syncthreads();
        float gxn;
        {
            float sn1 = 0.f;
#pragma unroll
            for (int j = 0; j < 8; ++j) {
                int p = lane + 32 * j;
                float4 y4 = ((const float4*)y_s)[p];
                float4 w4 = ((const float4*)w1n_row)[p];
                sn1 += w4.x * y4.x + w4.y * y4.y + w4.z * y4.z + w4.w * y4.w;
            }
#pragma unroll
            for (int o = 16; o > 0; o >>= 1) sn1 += __shfl_xor_sync(0xffffffffu, sn1, o);
            gxn = sn1 + b1n;
            if (warp == 0 && lane == 0) gxn0_p[0] = gxn;
        }
        float gxr = __ldcg(d_gx1 + u), gxz = __ldcg(d_gx1 + Hdim + u);
        __syncthreads();

        for (int s = 0; s < Tlen; ++s) {
            // dual broadcast: h1[s] (tid<256) and y1[s+1] (tid>=256)
            if (tid < 256) {
                float4 v = __ldcg(((const float4*)g_h1[s & 1]) + tid);
                *(float4*)(h_s + tid * 4) = v;
            } else if (s + 1 < Tlen) {
                int tt = tid - 256;
                float4 v = __ldcg(((const float4*)(d_y1 + (size_t)(s + 1) * Hdim)) + tt);
                *(float4*)(y_s + tt * 4) = v;
            }
            __syncthreads();
            float sr = 0.f, sz = 0.f, sn = 0.f;
#pragma unroll
            for (int j = 0; j < 8; ++j) {
                float4 h4 = ((const float4*)h_s)[lane + 32 * j];
                sr += wr[j].x * h4.x + wr[j].y * h4.y + wr[j].z * h4.z + wr[j].w * h4.w;
                sz += wz[j].x * h4.x + wz[j].y * h4.y + wz[j].z * h4.z + wz[j].w * h4.w;
                sn += wn[j].x * h4.x + wn[j].y * h4.y + wn[j].z * h4.z + wn[j].w * h4.w;
            }
#pragma unroll
            for (int o = 16; o > 0; o >>= 1) {
                sr += __shfl_xor_sync(0xffffffffu, sr, o);
                sz += __shfl_xor_sync(0xffffffffu, sz, o);
                sn += __shfl_xor_sync(0xffffffffu, sn, o);
            }
            if (lane == 0) {
                float use_gxn = (warp == 0) ? gxn0_p[0] : gxn;
                float r = sigmoidf_(gxr + sr + br);
                float z = sigmoidf_(gxz + sz + bz);
                float nn = tanhf(use_gxn + r * (sn + bn));
                float hp = h_s[u];
                float hnew = (1.0f - z) * nn + z * hp;
                g_h1[(s + 1) & 1][u] = hnew;
                d_wout[(size_t)s * Hdim + u] = hnew;
            }
            __syncthreads();
            // slack: n-gate inputs for step s+1 from y_s = y1[s+1].
            // warps 1..15 ONLY (warp 0's arrival must not be delayed);
            // warp 1 also covers unit 0, handing off through smem.
            if (s + 1 < Tlen && warp != 0) {
                float sn1 = 0.f;
#pragma unroll
                for (int j = 0; j < 8; ++j) {
                    int p = lane + 32 * j;
                    float4 y4 = ((const float4*)y_s)[p];
                    float4 w4 = ((const float4*)w1n_row)[p];
                    sn1 += w4.x * y4.x + w4.y * y4.y + w4.z * y4.z + w4.w * y4.w;
                }
#pragma unroll
                for (int o = 16; o > 0; o >>= 1) sn1 += __shfl_xor_sync(0xffffffffu, sn1, o);
                gxn = sn1 + b1n;
                if (warp == 1) {
                    float sn0 = 0.f;
#pragma unroll
                    for (int j = 0; j < 8; ++j) {
                        int p = lane + 32 * j;
                        float4 y4 = ((const float4*)y_s)[p];
                        float4 w4 = ((const float4*)w1n)[p];          // row 0
                        sn0 += w4.x * y4.x + w4.y * y4.y + w4.z * y4.z + w4.w * y4.w;
                    }
#pragma unroll
                    for (int o = 16; o > 0; o >>= 1) sn0 += __shfl_xor_sync(0xffffffffu, sn0, o);
                    if (lane == 0) gxn0_p[0] = sn0 + b1n0;
                }
            }
            if (tid == 0) {
                red_add_release(&cnt1[s], 1u);
                while (ld_acquire(&cnt1[s]) < (unsigned)RCTAS) { }
                if (s + 1 < Tlen) {
                    int ws = s + 3 < Tlen ? s + 3 : Tlen;   // gx1 r,z [s+1] gate
                    while (ld_acquire(&cnt0[ws]) < (unsigned)RCTAS) { }
                }
            }
            __syncthreads();
            if (s + 1 < Tlen) {
                const float* gp = d_gx1 + (size_t)(s + 1) * G3;
                gxr = __ldcg(gp + u); gxz = __ldcg(gp + Hdim + u);
            }
        }
    }
}

// ---------------- losses ----------------
__global__ void loss_kernel() {
    int n = blockIdx.x, tid = threadIdx.x;            // 256 threads
    int warp = tid >> 5, lane = tid & 31;
    float sr = 0.f, sw = 0.f;
    for (int i = tid; i < Hdim; i += 256) {
        float s = d_samples[(size_t)n * Hdim + i];
        float a = d_recon[(size_t)n * Hdim + i] - s;
        float b = d_wout[(size_t)n * Hdim + i] - s;
        sr += a * a;
        sw += b * b;
    }
    float mu = d_encoded[(size_t)n * H2 + tid];
    float lv = d_encoded[(size_t)n * H2 + 256 + tid];
    float sk = 1.0f + lv - mu * mu - expf(lv);
    __shared__ float rbuf[24];
#pragma unroll
    for (int o = 16; o > 0; o >>= 1) {
        sr += __shfl_xor_sync(0xffffffffu, sr, o);
        sw += __shfl_xor_sync(0xffffffffu, sw, o);
        sk += __shfl_xor_sync(0xffffffffu, sk, o);
    }
    if (lane == 0) { rbuf[warp] = sr; rbuf[8 + warp] = sw; rbuf[16 + warp] = sk; }
    __syncthreads();
    if (tid == 0) {
        float tr = 0.f, tw = 0.f, tk = 0.f;
        for (int w = 0; w < 8; ++w) { tr += rbuf[w]; tw += rbuf[8 + w]; tk += rbuf[16 + w]; }
        d_toterr[n] = tr * (1.0f / 1024.0f) + 0.1f * tw * (1.0f / 1024.0f)
                    + 0.001f * (-0.5f * tk);
    }
}

__global__ void mean_kernel(float* __restrict__ out) {
    int tid = threadIdx.x;                            // 256
    int warp = tid >> 5, lane = tid & 31;
    float s = 0.f;
    for (int i = tid; i < Nsamp; i += 256) s += d_toterr[i];
    __shared__ float rbuf[8];
#pragma unroll
    for (int o = 16; o > 0; o >>= 1) s += __shfl_xor_sync(0xffffffffu, s, o);
    if (lane == 0) rbuf[warp] = s;
    __syncthreads();
    if (tid == 0) {
        float t = 0.f;
        for (int w = 0; w < 8; ++w) t += rbuf[w];
        out[0] = t * (1.0f / (float)Nsamp);
    }
}

__global__ void copy_imp_kernel(const float* __restrict__ imp, float* __restrict__ out) {
    int i = blockIdx.x * blockDim.x + threadIdx.x;
    if (i < Msize) out[1 + i] = imp[i];
}

// duplicate indices: last occurrence in idx order wins (serial scatter semantics)
__global__ void scatter_kernel(const int* __restrict__ idx, const float* __restrict__ imp,
                               float* __restrict__ out) {
    int i = blockIdx.x * blockDim.x + threadIdx.x;
    if (i < Nsamp) {
        int d = idx[i];
        bool last = true;
        for (int j = i + 1; j < Nsamp; ++j)
            if (idx[j] == d) { last = false; break; }
        if (last) out[1 + d] = 0.9f * imp[d] + 0.1f * d_toterr[i];
    }
}

// ---------------- launch ----------------
extern "C" void kernel_launch(void* const* d_in, const int* in_sizes, int n_in,
                              void* d_out, int out_size) {
    (void)n_in; (void)out_size;
    const float *episodic, *memimp, *eps;
    const int* idx;
    const float *enc_w1, *enc_b1, *enc_g, *enc_beta, *enc_w2, *enc_b2;
    const float *dec_w1, *dec_b1, *dec_g, *dec_beta, *dec_w2, *dec_b2;
    const float *wih0, *whh0, *bih0, *bhh0, *wih1, *whh1, *bih1, *bhh1;

    if (in_sizes[3] == Nsamp) {
        episodic = (const float*)d_in[0];  memimp = (const float*)d_in[1];
        eps = (const float*)d_in[2];       idx = (const int*)d_in[3];
        enc_w1 = (const float*)d_in[4];    enc_b1 = (const float*)d_in[5];
        enc_g = (const float*)d_in[6];     enc_beta = (const float*)d_in[7];
        enc_w2 = (const float*)d_in[8];    enc_b2 = (const float*)d_in[9];
        dec_w1 = (const float*)d_in[10];   dec_b1 = (const float*)d_in[11];
        dec_g = (const float*)d_in[12];    dec_beta = (const float*)d_in[13];
        dec_w2 = (const float*)d_in[14];   dec_b2 = (const float*)d_in[15];
        wih0 = (const float*)d_in[16];     whh0 = (const float*)d_in[17];
        bih0 = (const float*)d_in[18];     bhh0 = (const float*)d_in[19];
        wih1 = (const float*)d_in[20];     whh1 = (const float*)d_in[21];
        bih1 = (const float*)d_in[22];     bhh1 = (const float*)d_in[23];
    } else {
        episodic = (const float*)d_in[0];  memimp = (const float*)d_in[1];
        eps = (const float*)d_in[2];
        enc_w1 = (const float*)d_in[3];    enc_b1 = (const float*)d_in[4];
        enc_g = (const float*)d_in[5];     enc_beta = (const float*)d_in[6];
        enc_w2 = (const float*)d_in[7];    enc_b2 = (const float*)d_in[8];
        dec_w1 = (const float*)d_in[9];    dec_b1 = (const float*)d_in[10];
        dec_g = (const float*)d_in[11];    dec_beta = (const float*)d_in[12];
        dec_w2 = (const float*)d_in[13];   dec_b2 = (const float*)d_in[14];
        wih0 = (const float*)d_in[15];     whh0 = (const float*)d_in[16];
        bih0 = (const float*)d_in[17];     bhh0 = (const float*)d_in[18];
        wih1 = (const float*)d_in[19];     whh1 = (const float*)d_in[20];
        bih1 = (const float*)d_in[21];     bhh1 = (const float*)d_in[22];
        idx = (const int*)d_in[23];
    }
    float* out = (float*)d_out;

    float *p_samples, *p_e1, *p_encoded, *p_z, *p_d1, *p_recon, *p_gx;
    cudaGetSymbolAddress((void**)&p_samples, d_samples);
    cudaGetSymbolAddress((void**)&p_e1, d_e1);
    cudaGetSymbolAddress((void**)&p_encoded, d_encoded);
    cudaGetSymbolAddress((void**)&p_z, d_zbuf);
    cudaGetSymbolAddress((void**)&p_d1, d_d1);
    cudaGetSymbolAddress((void**)&p_recon, d_recon);
    cudaGetSymbolAddress((void**)&p_gx, d_gx);

    // role 0: Hdim + 32*Hdim; role 1: 2*Hdim + 16*Hdim + 1 -> 33*Hdim covers both
    const size_t pipe_smem = (size_t)(33 * Hdim) * sizeof(float);   // 135168
    cudaFuncSetAttribute(gru_pipe_kernel, cudaFuncAttributeMaxDynamicSharedMemorySize,
                         (int)pipe_smem);

    init_kernel<<<8, 256>>>();
    gather_kernel<<<Nsamp, 256>>>(episodic, idx);

    // encoder
    sgemm_bias_kernel<<<dim3(H2 / TBN, Nsamp / TBM), 256>>>(p_samples, enc_w1, enc_b1, p_e1,
                                                            Nsamp, H2, Hdim);
    ln_gelu_kernel<<<Nsamp, 128>>>(p_e1, enc_g, enc_beta);
    sgemm_bias_kernel<<<dim3(H2 / TBN, Nsamp / TBM), 256>>>(p_e1, enc_w2, enc_b2, p_encoded,
                                                            Nsamp, H2, H2);
    reparam_kernel<<<(Nsamp * Cdim) / 256, 256>>>(eps);

    // decoder
    sgemm_bias_kernel<<<dim3(H2 / TBN, Nsamp / TBM), 256>>>(p_z, dec_w1, dec_b1, p_d1,
                                                            Nsamp, H2, Cdim);
    ln_gelu_kernel<<<Nsamp, 128>>>(p_d1, dec_g, dec_beta);
    sgemm_bias_kernel<<<dim3(Hdim / TBN, Nsamp / TBM), 256>>>(p_d1, dec_w2, dec_b2, p_recon,
                                                              Nsamp, Hdim, H2);

    // layer-0 input gates, then BOTH GRU layers pipelined in one kernel
    sgemm_bias_kernel<<<dim3(G3 / TBN, Nsamp / TBM), 256>>>(p_recon, wih0, bih0, p_gx,
                                                            Nsamp, G3, Hdim);
    gru_pipe_kernel<<<2 * RCTAS, 512, pipe_smem>>>(whh0, bhh0, whh1, bhh1, wih1, bih1);

    // losses + outputs
    loss_kernel<<<Nsamp, 256>>>();
    mean_kernel<<<1, 256>>>(out);
    copy_imp_kernel<<<(Msize + 255) / 256, 256>>>(memimp, out);
    scatter_kernel<<<4, 256>>>(idx, memimp, out);
}

// round 15
// speedup vs baseline: 1.1597x; 1.1597x over previous
#include <cuda_runtime.h>
#include <math.h>

#define Hdim   1024
#define H2     512
#define Cdim   256
#define Msize  100000
#define Nsamp  1024
#define Tlen   1024
#define G3     3072
#define RCTAS  64           // CTAs per layer (total grid = 128)
#define RUPC   16           // hidden units per CTA (one per warp, 512 threads)

// ---------------- scratch (static __device__, no allocs) ----------------
__device__ __align__(16) float d_samples[Nsamp * Hdim];
__device__ __align__(16) float d_e1[Nsamp * H2];
__device__ __align__(16) float d_encoded[Nsamp * H2];
__device__ __align__(16) float d_zbuf[Nsamp * Cdim];
__device__ __align__(16) float d_d1[Nsamp * H2];
__device__ __align__(16) float d_recon[Nsamp * Hdim];
__device__ __align__(16) float d_gx[Tlen * G3];        // layer-0 input gates (GEMM)
__device__ __align__(16) float d_gx1[Tlen * G3];       // layer-1 input gates (fused)
__device__ __align__(16) float d_wout[Tlen * Hdim];
__device__ float d_toterr[Nsamp];
__device__ __align__(16) float g_h0[2][Hdim];
__device__ __align__(16) float g_h1[2][Hdim];
__device__ unsigned cnt0[Tlen + 1];
__device__ unsigned cnt1[Tlen];

__device__ __forceinline__ float gelu_exact(float x) {
    return 0.5f * x * (1.0f + erff(x * 0.7071067811865476f));
}
__device__ __forceinline__ float sigmoidf_(float x) {
    return 1.0f / (1.0f + expf(-x));
}
__device__ __forceinline__ void red_add_release(unsigned* p, unsigned v) {
    asm volatile("red.add.release.gpu.global.u32 [%0], %1;" :: "l"(p), "r"(v) : "memory");
}
__device__ __forceinline__ unsigned ld_acquire(const unsigned* p) {
    unsigned v;
    asm volatile("ld.acquire.gpu.global.u32 %0, [%1];" : "=r"(v) : "l"(p) : "memory");
    return v;
}

// ---------------- init / small utility kernels ----------------
__global__ void init_kernel() {
    int i = blockIdx.x * blockDim.x + threadIdx.x;    // 8 x 256 = 2048
    if (i < 2 * Hdim) {
        ((float*)g_h0)[i] = 0.0f;
        ((float*)g_h1)[i] = 0.0f;
    }
    if (i < Tlen + 1) cnt0[i] = 0u;
    if (i < Tlen) cnt1[i] = 0u;
}

__global__ void gather_kernel(const float* __restrict__ mem, const int* __restrict__ idx) {
    int n = blockIdx.x;                               // 1024 blocks, 256 threads
    const float4* src = (const float4*)(mem + (size_t)idx[n] * Hdim);
    float4* dst = (float4*)(d_samples + (size_t)n * Hdim);
    dst[threadIdx.x] = src[threadIdx.x];
}

// ---------------- SGEMM 128x128x8, double-buffered: C = A@W^T + bias -------
#define TBM 128
#define TBN 128
#define TBK 8
__global__ void __launch_bounds__(256)
sgemm_bias_kernel(const float* __restrict__ A, const float* __restrict__ W,
                  const float* __restrict__ bias, float* __restrict__ C,
                  int M, int N, int K) {
    __shared__ float As[2][TBK][TBM];
    __shared__ float Bs[2][TBK][TBN];
    const int tid = threadIdx.x;                      // 256
    const int tx = tid & 15, ty = tid >> 4;
    const int row0 = blockIdx.y * TBM, col0 = blockIdx.x * TBN;
    const int lr = tid >> 1;                          // 0..127
    const int lk = (tid & 1) * 4;                     // 0 or 4
    const float* Ap = A + (size_t)(row0 + lr) * K + lk;
    const float* Wp = W + (size_t)(col0 + lr) * K + lk;

    {
        float4 a = *(const float4*)Ap;
        float4 b = *(const float4*)Wp;
        As[0][lk + 0][lr] = a.x; As[0][lk + 1][lr] = a.y;
        As[0][lk + 2][lr] = a.z; As[0][lk + 3][lr] = a.w;
        Bs[0][lk + 0][lr] = b.x; Bs[0][lk + 1][lr] = b.y;
        Bs[0][lk + 2][lr] = b.z; Bs[0][lk + 3][lr] = b.w;
    }
    __syncthreads();

    float acc[8][8];
#pragma unroll
    for (int i = 0; i < 8; i++)
#pragma unroll
        for (int j = 0; j < 8; j++) acc[i][j] = 0.0f;

    const int nIter = K / TBK;
    int cur = 0;
    for (int it = 0; it < nIter; ++it) {
        float4 an, bn;
        const bool more = (it + 1 < nIter);
        if (more) {
            an = *(const float4*)(Ap + (it + 1) * TBK);
            bn = *(const float4*)(Wp + (it + 1) * TBK);
        }
#pragma unroll
        for (int k = 0; k < TBK; k++) {
            float af[8], bf[8];
            *(float4*)&af[0] = *(const float4*)&As[cur][k][ty * 8];
            *(float4*)&af[4] = *(const float4*)&As[cur][k][ty * 8 + 4];
            *(float4*)&bf[0] = *(const float4*)&Bs[cur][k][tx * 8];
            *(float4*)&bf[4] = *(const float4*)&Bs[cur][k][tx * 8 + 4];
#pragma unroll
            for (int i = 0; i < 8; i++)
#pragma unroll
                for (int j = 0; j < 8; j++) acc[i][j] += af[i] * bf[j];
        }
        if (more) {
            int nxt = cur ^ 1;
            As[nxt][lk + 0][lr] = an.x; As[nxt][lk + 1][lr] = an.y;
            As[nxt][lk + 2][lr] = an.z; As[nxt][lk + 3][lr] = an.w;
            Bs[nxt][lk + 0][lr] = bn.x; Bs[nxt][lk + 1][lr] = bn.y;
            Bs[nxt][lk + 2][lr] = bn.z; Bs[nxt][lk + 3][lr] = bn.w;
            __syncthreads();
            cur = nxt;
        }
    }

    float bc[8];
#pragma unroll
    for (int j = 0; j < 8; j++) bc[j] = bias[col0 + tx * 8 + j];
#pragma unroll
    for (int i = 0; i < 8; i++) {
        float* Cr = C + (size_t)(row0 + ty * 8 + i) * N + col0 + tx * 8;
        float4 v0 = make_float4(acc[i][0] + bc[0], acc[i][1] + bc[1],
                                acc[i][2] + bc[2], acc[i][3] + bc[3]);
        float4 v1 = make_float4(acc[i][4] + bc[4], acc[i][5] + bc[5],
                                acc[i][6] + bc[6], acc[i][7] + bc[7]);
        *(float4*)Cr = v0;
        *(float4*)(Cr + 4) = v1;
    }
}

// ---------------- LayerNorm(512) + exact GELU, in place ----------------
__global__ void ln_gelu_kernel(float* __restrict__ x, const float* __restrict__ g,
                               const float* __restrict__ b) {
    int row = blockIdx.x, tid = threadIdx.x;          // 128 threads, 4 elems each
    float4* xr = (float4*)(x + (size_t)row * H2);
    float4 v = xr[tid];
    float s = v.x + v.y + v.z + v.w;
    __shared__ float red[8];
#pragma unroll
    for (int o = 16; o > 0; o >>= 1) s += __shfl_xor_sync(0xffffffffu, s, o);
    if ((tid & 31) == 0) red[tid >> 5] = s;
    __syncthreads();
    float mean = (red[0] + red[1] + red[2] + red[3]) * (1.0f / 512.0f);
    float dx = v.x - mean, dy = v.y - mean, dz = v.z - mean, dw = v.w - mean;
    float q = dx * dx + dy * dy + dz * dz + dw * dw;
#pragma unroll
    for (int o = 16; o > 0; o >>= 1) q += __shfl_xor_sync(0xffffffffu, q, o);
    if ((tid & 31) == 0) red[4 + (tid >> 5)] = q;
    __syncthreads();
    float var = (red[4] + red[5] + red[6] + red[7]) * (1.0f / 512.0f);
    float rstd = rsqrtf(var + 1e-5f);
    float4 gg = ((const float4*)g)[tid];
    float4 bb = ((const float4*)b)[tid];
    v.x = gelu_exact(dx * rstd * gg.x + bb.x);
    v.y = gelu_exact(dy * rstd * gg.y + bb.y);
    v.z = gelu_exact(dz * rstd * gg.z + bb.z);
    v.w = gelu_exact(dw * rstd * gg.w + bb.w);
    xr[tid] = v;
}

// ---------------- reparameterize ----------------
__global__ void reparam_kernel(const float* __restrict__ eps) {
    int i = blockIdx.x * blockDim.x + threadIdx.x;    // N*C = 262144
    if (i < Nsamp * Cdim) {
        int n = i >> 8, c = i & 255;
        float mu = d_encoded[(size_t)n * H2 + c];
        float lv = d_encoded[(size_t)n * H2 + 256 + c];
        d_zbuf[i] = mu + expf(0.5f * lv) * eps[i];
    }
}

// ---------------- pipelined 2-layer GRU recurrence (R12 structure) ----------
// Grid = 128 CTAs x 512 threads, all co-resident.
// CTAs 0..63   (role 0): layer-0 recurrence; ALL 48 gx1 rows computed by warps
//   1..15 during the barrier spin window (warp 0 arrives immediately).
// CTAs 64..127 (role 1): lean layer-1 recurrence; thread0's two waits merged
//   into one combined poll.
__global__ void __launch_bounds__(512, 1)
gru_pipe_kernel(const float* __restrict__ whh0, const float* __restrict__ bhh0,
                const float* __restrict__ whh1, const float* __restrict__ bhh1,
                const float* __restrict__ wih1, const float* __restrict__ bih1) {
    extern __shared__ float smem_dyn[];
    float* h_s = smem_dyn;                    // Hdim
    float* w1s = smem_dyn + Hdim;             // 48*Hdim (role 0 only)
    const int tid = threadIdx.x;
    const int warp = tid >> 5, lane = tid & 31;
    const bool role1 = (blockIdx.x >= RCTAS);
    const int cid = role1 ? (blockIdx.x - RCTAS) : blockIdx.x;
    const int u = cid * RUPC + warp;
    const float* whh = role1 ? whh1 : whh0;
    const float* bhh = role1 ? bhh1 : bhh0;

    // whh rows (r,z,n) for unit u -> registers. lane l owns cols k = 4l + 128j.
    float4 wr[8], wz[8], wn[8];
#pragma unroll
    for (int j = 0; j < 8; j++) {
        int k = 4 * lane + 128 * j;
        wr[j] = __ldg((const float4*)(whh + (size_t)(0 * Hdim + u) * Hdim + k));
        wz[j] = __ldg((const float4*)(whh + (size_t)(1 * Hdim + u) * Hdim + k));
        wn[j] = __ldg((const float4*)(whh + (size_t)(2 * Hdim + u) * Hdim + k));
    }
    const float br = bhh[u], bz = bhh[Hdim + u], bn = bhh[2 * Hdim + u];

    if (!role1) {
        // ---- layer 0 ----
        // wih1 rows for units 16*cid..16*cid+15 (48 rows) -> smem
        for (int i = tid; i < 48 * 256; i += 512) {
            int lr = i >> 8, pos = (i & 255) << 2;
            int grow = (lr >> 4) * Hdim + RUPC * cid + (lr & 15);
            *(float4*)(w1s + lr * Hdim + pos) =
                __ldg((const float4*)(wih1 + (size_t)grow * Hdim + pos));
        }
        // per-warp gx1 row assignment: warps 1..15 handle rows base, base+15,
        // base+30, base+45(if<48), base = warp-1
        const int base = warp - 1;
        float b1a = 0.f, b1b = 0.f, b1c = 0.f, b1d = 0.f;
        if (warp >= 1) {
            b1a = bih1[(base >> 4) * Hdim + RUPC * cid + (base & 15)];
            b1b = bih1[((base + 15) >> 4) * Hdim + RUPC * cid + ((base + 15) & 15)];
            b1c = bih1[((base + 30) >> 4) * Hdim + RUPC * cid + ((base + 30) & 15)];
            if (base + 45 < 48)
                b1d = bih1[((base + 45) >> 4) * Hdim + RUPC * cid + ((base + 45) & 15)];
        }
        __syncthreads();

        auto gx1_rows = [&](int tout) {
            const float* r0 = w1s + base * Hdim;
            const float* r1 = w1s + (base + 15) * Hdim;
            const float* r2 = w1s + (base + 30) * Hdim;
            const float* r3 = (base + 45 < 48) ? (w1s + (base + 45) * Hdim) : r0;
            float p0 = 0.f, p1 = 0.f, p2 = 0.f, p3 = 0.f;
#pragma unroll
            for (int j = 0; j < 8; ++j) {
                int p = lane + 32 * j;
                float4 h4 = ((const float4*)h_s)[p];
                float4 a = ((const float4*)r0)[p];
                float4 b = ((const float4*)r1)[p];
                float4 c = ((const float4*)r2)[p];
                float4 d = ((const float4*)r3)[p];
                p0 += a.x * h4.x + a.y * h4.y + a.z * h4.z + a.w * h4.w;
                p1 += b.x * h4.x + b.y * h4.y + b.z * h4.z + b.w * h4.w;
                p2 += c.x * h4.x + c.y * h4.y + c.z * h4.z + c.w * h4.w;
                p3 += d.x * h4.x + d.y * h4.y + d.z * h4.z + d.w * h4.w;
            }
#pragma unroll
            for (int o = 16; o > 0; o >>= 1) {
                p0 += __shfl_xor_sync(0xffffffffu, p0, o);
                p1 += __shfl_xor_sync(0xffffffffu, p1, o);
                p2 += __shfl_xor_sync(0xffffffffu, p2, o);
                p3 += __shfl_xor_sync(0xffffffffu, p3, o);
            }
            if (lane == 0) {
                size_t ob = (size_t)tout * G3;
                d_gx1[ob + (base >> 4) * Hdim + RUPC * cid + (base & 15)] = p0 + b1a;
                d_gx1[ob + ((base + 15) >> 4) * Hdim + RUPC * cid + ((base + 15) & 15)] = p1 + b1b;
                d_gx1[ob + ((base + 30) >> 4) * Hdim + RUPC * cid + ((base + 30) & 15)] = p2 + b1c;
                if (base + 45 < 48)
                    d_gx1[ob + ((base + 45) >> 4) * Hdim + RUPC * cid + ((base + 45) & 15)] = p3 + b1d;
            }
        };

        float gxr = __ldg(d_gx + u), gxz = __ldg(d_gx + Hdim + u),
              gxn = __ldg(d_gx + 2 * Hdim + u);

        for (int t = 0; t < Tlen; ++t) {
            if (tid < 256) {
                float4 v = __ldcg(((const float4*)g_h0[t & 1]) + tid);
                *(float4*)(h_s + tid * 4) = v;
            }
            __syncthreads();
            float sr = 0.f, sz = 0.f, sn = 0.f;
#pragma unroll
            for (int j = 0; j < 8; ++j) {
                float4 h4 = ((const float4*)h_s)[lane + 32 * j];
                sr += wr[j].x * h4.x + wr[j].y * h4.y + wr[j].z * h4.z + wr[j].w * h4.w;
                sz += wz[j].x * h4.x + wz[j].y * h4.y + wz[j].z * h4.z + wz[j].w * h4.w;
                sn += wn[j].x * h4.x + wn[j].y * h4.y + wn[j].z * h4.z + wn[j].w * h4.w;
            }
#pragma unroll
            for (int o = 16; o > 0; o >>= 1) {
                sr += __shfl_xor_sync(0xffffffffu, sr, o);
                sz += __shfl_xor_sync(0xffffffffu, sz, o);
                sn += __shfl_xor_sync(0xffffffffu, sn, o);
            }
            if (lane == 0) {
                float r = sigmoidf_(gxr + sr + br);
                float z = sigmoidf_(gxz + sz + bz);
                float nn = tanhf(gxn + r * (sn + bn));
                float hp = h_s[u];
                float hnew = (1.0f - z) * nn + z * hp;
                g_h0[(t + 1) & 1][u] = hnew;
            }
            if (t + 1 < Tlen) {
                const float* gp = d_gx + (size_t)(t + 1) * G3;
                gxr = __ldg(gp + u); gxz = __ldg(gp + Hdim + u); gxn = __ldg(gp + 2 * Hdim + u);
            }
            __syncthreads();
            if (t > 0 && warp != 0) gx1_rows(t - 1);   // slack work (h_s = y1[t-1])
            if (tid == 0) {
                red_add_release(&cnt0[t], 1u);
                while (ld_acquire(&cnt0[t]) < (unsigned)RCTAS) { }
            }
            __syncthreads();
        }
        // epilogue: gx1[Tlen-1] from h_Tlen
        if (tid < 256) {
            float4 v = __ldcg(((const float4*)g_h0[Tlen & 1]) + tid);
            *(float4*)(h_s + tid * 4) = v;
        }
        __syncthreads();
        if (warp != 0) gx1_rows(Tlen - 1);
        __syncthreads();
        if (tid == 0) red_add_release(&cnt0[Tlen], 1u);
    } else {
        // ---- layer 1 ----
        // wait for gx1[0] availability (ordered by cnt0[2])
        if (tid == 0) {
            while (ld_acquire(&cnt0[2]) < (unsigned)RCTAS) { }
        }
        __syncthreads();
        float gxr = __ldcg(d_gx1 + u), gxz = __ldcg(d_gx1 + Hdim + u),
              gxn = __ldcg(d_gx1 + 2 * Hdim + u);

        for (int s = 0; s < Tlen; ++s) {
            if (tid < 256) {
                float4 v = __ldcg(((const float4*)g_h1[s & 1]) + tid);
                *(float4*)(h_s + tid * 4) = v;
            }
            __syncthreads();
            float sr = 0.f, sz = 0.f, sn = 0.f;
#pragma unroll
            for (int j = 0; j < 8; ++j) {
                float4 h4 = ((const float4*)h_s)[lane + 32 * j];
                sr += wr[j].x * h4.x + wr[j].y * h4.y + wr[j].z * h4.z + wr[j].w * h4.w;
                sz += wz[j].x * h4.x + wz[j].y * h4.y + wz[j].z * h4.z + wz[j].w * h4.w;
                sn += wn[j].x * h4.x + wn[j].y * h4.y + wn[j].z * h4.z + wn[j].w * h4.w;
            }
#pragma unroll
            for (int o = 16; o > 0; o >>= 1) {
                sr += __shfl_xor_sync(0xffffffffu, sr, o);
                sz += __shfl_xor_sync(0xffffffffu, sz, o);
                sn += __shfl_xor_sync(0xffffffffu, sn, o);
            }
            if (lane == 0) {
                float r = sigmoidf_(gxr + sr + br);
                float z = sigmoidf_(gxz + sz + bz);
                float nn = tanhf(gxn + r * (sn + bn));
                float hp = h_s[u];
                float hnew = (1.0f - z) * nn + z * hp;
                g_h1[(s + 1) & 1][u] = hnew;
                d_wout[(size_t)s * Hdim + u] = hnew;
            }
            __syncthreads();
            if (tid == 0) {
                red_add_release(&cnt1[s], 1u);
                // combined poll: own barrier AND next gx1 availability
                if (s + 1 < Tlen) {
                    int ws = s + 3 < Tlen ? s + 3 : Tlen;
                    bool a = false, b = false;
                    for (;;) {
                        if (!a) a = (ld_acquire(&cnt1[s]) >= (unsigned)RCTAS);
                        if (!b) b = (ld_acquire(&cnt0[ws]) >= (unsigned)RCTAS);
                        if (a && b) break;
                    }
                } else {
                    while (ld_acquire(&cnt1[s]) < (unsigned)RCTAS) { }
                }
            }
            __syncthreads();
            if (s + 1 < Tlen) {
                const float* gp = d_gx1 + (size_t)(s + 1) * G3;
                gxr = __ldcg(gp + u); gxz = __ldcg(gp + Hdim + u);
                gxn = __ldcg(gp + 2 * Hdim + u);
            }
        }
    }
}

// ---------------- losses ----------------
__global__ void loss_kernel() {
    int n = blockIdx.x, tid = threadIdx.x;            // 256 threads
    int warp = tid >> 5, lane = tid & 31;
    float sr = 0.f, sw = 0.f;
    for (int i = tid; i < Hdim; i += 256) {
        float s = d_samples[(size_t)n * Hdim + i];
        float a = d_recon[(size_t)n * Hdim + i] - s;
        float b = d_wout[(size_t)n * Hdim + i] - s;
        sr += a * a;
        sw += b * b;
    }
    float mu = d_encoded[(size_t)n * H2 + tid];
    float lv = d_encoded[(size_t)n * H2 + 256 + tid];
    float sk = 1.0f + lv - mu * mu - expf(lv);
    __shared__ float rbuf[24];
#pragma unroll
    for (int o = 16; o > 0; o >>= 1) {
        sr += __shfl_xor_sync(0xffffffffu, sr, o);
        sw += __shfl_xor_sync(0xffffffffu, sw, o);
        sk += __shfl_xor_sync(0xffffffffu, sk, o);
    }
    if (lane == 0) { rbuf[warp] = sr; rbuf[8 + warp] = sw; rbuf[16 + warp] = sk; }
    __syncthreads();
    if (tid == 0) {
        float tr = 0.f, tw = 0.f, tk = 0.f;
        for (int w = 0; w < 8; ++w) { tr += rbuf[w]; tw += rbuf[8 + w]; tk += rbuf[16 + w]; }
        d_toterr[n] = tr * (1.0f / 1024.0f) + 0.1f * tw * (1.0f / 1024.0f)
                    + 0.001f * (-0.5f * tk);
    }
}

__global__ void mean_kernel(float* __restrict__ out) {
    int tid = threadIdx.x;                            // 256
    int warp = tid >> 5, lane = tid & 31;
    float s = 0.f;
    for (int i = tid; i < Nsamp; i += 256) s += d_toterr[i];
    __shared__ float rbuf[8];
#pragma unroll
    for (int o = 16; o > 0; o >>= 1) s += __shfl_xor_sync(0xffffffffu, s, o);
    if (lane == 0) rbuf[warp] = s;
    __syncthreads();
    if (tid == 0) {
        float t = 0.f;
        for (int w = 0; w < 8; ++w) t += rbuf[w];
        out[0] = t * (1.0f / (float)Nsamp);
    }
}

__global__ void copy_imp_kernel(const float* __restrict__ imp, float* __restrict__ out) {
    int i = blockIdx.x * blockDim.x + threadIdx.x;
    if (i < Msize) out[1 + i] = imp[i];
}

// duplicate indices: last occurrence in idx order wins (serial scatter semantics)
__global__ void scatter_kernel(const int* __restrict__ idx, const float* __restrict__ imp,
                               float* __restrict__ out) {
    int i = blockIdx.x * blockDim.x + threadIdx.x;
    if (i < Nsamp) {
        int d = idx[i];
        bool last = true;
        for (int j = i + 1; j < Nsamp; ++j)
            if (idx[j] == d) { last = false; break; }
        if (last) out[1 + d] = 0.9f * imp[d] + 0.1f * d_toterr[i];
    }
}

// ---------------- launch ----------------
extern "C" void kernel_launch(void* const* d_in, const int* in_sizes, int n_in,
                              void* d_out, int out_size) {
    (void)n_in; (void)out_size;
    const float *episodic, *memimp, *eps;
    const int* idx;
    const float *enc_w1, *enc_b1, *enc_g, *enc_beta, *enc_w2, *enc_b2;
    const float *dec_w1, *dec_b1, *dec_g, *dec_beta, *dec_w2, *dec_b2;
    const float *wih0, *whh0, *bih0, *bhh0, *wih1, *whh1, *bih1, *bhh1;

    if (in_sizes[3] == Nsamp) {
        episodic = (const float*)d_in[0];  memimp = (const float*)d_in[1];
        eps = (const float*)d_in[2];       idx = (const int*)d_in[3];
        enc_w1 = (const float*)d_in[4];    enc_b1 = (const float*)d_in[5];
        enc_g = (const float*)d_in[6];     enc_beta = (const float*)d_in[7];
        enc_w2 = (const float*)d_in[8];    enc_b2 = (const float*)d_in[9];
        dec_w1 = (const float*)d_in[10];   dec_b1 = (const float*)d_in[11];
        dec_g = (const float*)d_in[12];    dec_beta = (const float*)d_in[13];
        dec_w2 = (const float*)d_in[14];   dec_b2 = (const float*)d_in[15];
        wih0 = (const float*)d_in[16];     whh0 = (const float*)d_in[17];
        bih0 = (const float*)d_in[18];     bhh0 = (const float*)d_in[19];
        wih1 = (const float*)d_in[20];     whh1 = (const float*)d_in[21];
        bih1 = (const float*)d_in[22];     bhh1 = (const float*)d_in[23];
    } else {
        episodic = (const float*)d_in[0];  memimp = (const float*)d_in[1];
        eps = (const float*)d_in[2];
        enc_w1 = (const float*)d_in[3];    enc_b1 = (const float*)d_in[4];
        enc_g = (const float*)d_in[5];     enc_beta = (const float*)d_in[6];
        enc_w2 = (const float*)d_in[7];    enc_b2 = (const float*)d_in[8];
        dec_w1 = (const float*)d_in[9];    dec_b1 = (const float*)d_in[10];
        dec_g = (const float*)d_in[11];    dec_beta = (const float*)d_in[12];
        dec_w2 = (const float*)d_in[13];   dec_b2 = (const float*)d_in[14];
        wih0 = (const float*)d_in[15];     whh0 = (const float*)d_in[16];
        bih0 = (const float*)d_in[17];     bhh0 = (const float*)d_in[18];
        wih1 = (const float*)d_in[19];     whh1 = (const float*)d_in[20];
        bih1 = (const float*)d_in[21];     bhh1 = (const float*)d_in[22];
        idx = (const int*)d_in[23];
    }
    float* out = (float*)d_out;

    float *p_samples, *p_e1, *p_encoded, *p_z, *p_d1, *p_recon, *p_gx;
    cudaGetSymbolAddress((void**)&p_samples, d_samples);
    cudaGetSymbolAddress((void**)&p_e1, d_e1);
    cudaGetSymbolAddress((void**)&p_encoded, d_encoded);
    cudaGetSymbolAddress((void**)&p_z, d_zbuf);
    cudaGetSymbolAddress((void**)&p_d1, d_d1);
    cudaGetSymbolAddress((void**)&p_recon, d_recon);
    cudaGetSymbolAddress((void**)&p_gx, d_gx);

    const size_t pipe_smem = (size_t)(Hdim + 48 * Hdim) * sizeof(float);   // 200704
    cudaFuncSetAttribute(gru_pipe_kernel, cudaFuncAttributeMaxDynamicSharedMemorySize,
                         (int)pipe_smem);

    init_kernel<<<8, 256>>>();
    gather_kernel<<<Nsamp, 256>>>(episodic, idx);

    // encoder
    sgemm_bias_kernel<<<dim3(H2 / TBN, Nsamp / TBM), 256>>>(p_samples, enc_w1, enc_b1, p_e1,
                                                            Nsamp, H2, Hdim);
    ln_gelu_kernel<<<Nsamp, 128>>>(p_e1, enc_g, enc_beta);
    sgemm_bias_kernel<<<dim3(H2 / TBN, Nsamp / TBM), 256>>>(p_e1, enc_w2, enc_b2, p_encoded,
                                                            Nsamp, H2, H2);
    reparam_kernel<<<(Nsamp * Cdim) / 256, 256>>>(eps);

    // decoder
    sgemm_bias_kernel<<<dim3(H2 / TBN, Nsamp / TBM), 256>>>(p_z, dec_w1, dec_b1, p_d1,
                                                            Nsamp, H2, Cdim);
    ln_gelu_kernel<<<Nsamp, 128>>>(p_d1, dec_g, dec_beta);
    sgemm_bias_kernel<<<dim3(Hdim / TBN, Nsamp / TBM), 256>>>(p_d1, dec_w2, dec_b2, p_recon,
                                                              Nsamp, Hdim, H2);

    // layer-0 input gates, then BOTH GRU layers pipelined in one kernel
    sgemm_bias_kernel<<<dim3(G3 / TBN, Nsamp / TBM), 256>>>(p_recon, wih0, bih0, p_gx,
                                                            Nsamp, G3, Hdim);
    gru_pipe_kernel<<<2 * RCTAS, 512, pipe_smem>>>(whh0, bhh0, whh1, bhh1, wih1, bih1);

    // losses + outputs
    loss_kernel<<<Nsamp, 256>>>();
    mean_kernel<<<1, 256>>>(out);
    copy_imp_kernel<<<(Msize + 255) / 256, 256>>>(memimp, out);
    scatter_kernel<<<4, 256>>>(idx, memimp, out);
}